// round 13
// baseline (speedup 1.0000x reference)
#include <cuda_runtime.h>
#include <cstdint>

#define B_SZ 8
#define SEQ 4096
#define DM 1024
#define DS 64
#define LTAPS 64

#define TBLK 128    // time steps per tile
#define NTILE 4     // tiles per CTA (sequential in t)
#define CBLK 64     // channels per block (32 float2 pairs)
#define TT 8        // outputs per thread
#define NTHR 512    // conv block size
#define G 8         // tap group size
#define ROWS (TBLK + 64)   // 192 rows per u tile (halo 32 each side)

__device__ float g_part[64 * DS];   // partial C column sums
__device__ float g_K[LTAPS * DM];   // K[l][c], channel-contiguous

// ---------------- packed f32x2 ops (Blackwell FFMA2, PTX-only) ----------------

__device__ __forceinline__ float2 ffma2(float2 a, float2 b, float2 c) {
    float2 d;
    asm("fma.rn.f32x2 %0, %1, %2, %3;"
        : "=l"(*reinterpret_cast<unsigned long long*>(&d))
        : "l"(*reinterpret_cast<const unsigned long long*>(&a)),
          "l"(*reinterpret_cast<const unsigned long long*>(&b)),
          "l"(*reinterpret_cast<const unsigned long long*>(&c)));
    return d;
}

__device__ __forceinline__ float2 fmul2(float2 a, float2 b) {
    float2 d;
    asm("mul.rn.f32x2 %0, %1, %2;"
        : "=l"(*reinterpret_cast<unsigned long long*>(&d))
        : "l"(*reinterpret_cast<const unsigned long long*>(&a)),
          "l"(*reinterpret_cast<const unsigned long long*>(&b)));
    return d;
}

// ---------------- prep: stage A — partial column sums of C (coalesced) --------
__global__ __launch_bounds__(64)
void csum_part_kernel(const float* __restrict__ C) {
    const int d = threadIdx.x;
    const float* __restrict__ Cp = C + (size_t)blockIdx.x * 16 * DS + d;
    float s = 0.f;
    #pragma unroll
    for (int i = 0; i < 16; ++i) s += Cp[(size_t)i * DS];
    g_part[blockIdx.x * DS + d] = s;
}

// ---------------- prep: stage B + K build (f32x2 geometric chains) ------------
__global__ __launch_bounds__(64)
void kbuild_kernel(const float* __restrict__ A,
                   const float* __restrict__ Bp,
                   const float* __restrict__ log_dt) {
    __shared__ float sh_csum[DS];
    const int tid = threadIdx.x;

    {
        float s = 0.f;
        #pragma unroll 16
        for (int j = 0; j < 64; ++j) s += g_part[j * DS + tid];
        sh_csum[tid] = s;
    }
    __syncthreads();

    const int c = blockIdx.x * 64 + tid;
    const float dt = expf(log_dt[c]);

    float2 k2[LTAPS / 2];
    #pragma unroll
    for (int i = 0; i < LTAPS / 2; ++i) k2[i] = make_float2(0.f, 0.f);

    #pragma unroll 2
    for (int d = 0; d < DS; ++d) {
        const float w  = sh_csum[d] * Bp[(size_t)d * DM + c];
        const float r  = expf(A[d] * dt);
        const float r2 = r * r;
        float2 p = make_float2(w, w * r);
        const float2 rr = make_float2(r2, r2);
        #pragma unroll
        for (int i = 0; i < LTAPS / 2; ++i) {
            k2[i].x += p.x;
            k2[i].y += p.y;
            p = fmul2(p, rr);
        }
    }

    #pragma unroll
    for (int i = 0; i < LTAPS / 2; ++i) {
        g_K[(size_t)(2 * i)     * DM + c] = k2[i].x;
        g_K[(size_t)(2 * i + 1) * DM + c] = k2[i].y;
    }
}

// ---------------- cp.async helpers ----------------

__device__ __forceinline__ void cp_async8(void* smem_dst, const void* gsrc,
                                          unsigned src_size) {
    unsigned daddr = (unsigned)__cvta_generic_to_shared(smem_dst);
    asm volatile("cp.async.ca.shared.global [%0], [%1], 8, %2;"
                 :: "r"(daddr), "l"(gsrc), "r"(src_size));
}

__device__ __forceinline__ void cp_commit() {
    asm volatile("cp.async.commit_group;");
}

template <int N>
__device__ __forceinline__ void cp_wait() {
    asm volatile("cp.async.wait_group %0;" :: "n"(N));
}

// ---------------- conv kernel ----------------
// y[b,t,c] = D[c]*u[b,t,c] + sum_{l=0}^{63} K[l,c] * u[b, t+31-l, c]
// R3 compute body (K from L2). u double-buffered via cp.async, 4 tiles/CTA.
// smem = 2 x 48KB = 96KB -> 2 CTAs/SM (192KB), 32 warps/SM preserved.

__global__ __launch_bounds__(NTHR, 2)
void conv_kernel(const float* __restrict__ u,
                 const float* __restrict__ Dp,
                 float* __restrict__ y) {
    extern __shared__ float2 dyn[];
    float2 (*buf0)[CBLK / 2] = reinterpret_cast<float2(*)[CBLK / 2]>(dyn);
    float2 (*buf1)[CBLK / 2] = reinterpret_cast<float2(*)[CBLK / 2]>(dyn + ROWS * 32);

    const int b     = blockIdx.z;
    const int tbase = blockIdx.x * (TBLK * NTILE);
    const int c0    = blockIdx.y * CBLK;
    const int tid   = threadIdx.x;

    const float2* __restrict__ u2 =
        reinterpret_cast<const float2*>(u + (size_t)b * SEQ * DM + c0);

    // issue tile 0 fill as group 0
    #pragma unroll
    for (int it = 0; it < ROWS * 32 / NTHR; ++it) {
        int i  = it * NTHR + tid;
        int tt = i >> 5;
        int pp = i & 31;
        int t  = tbase - 32 + tt;
        bool valid = (t >= 0) && (t < SEQ);
        cp_async8(&buf0[tt][pp],
                  u2 + (size_t)(valid ? t : 0) * (DM / 2) + pp,
                  valid ? 8u : 0u);
    }
    cp_commit();

    const int p   = tid & 31;          // channel pair
    const int tg  = tid >> 5;          // time group (0..15)
    const int lt0 = 32 + tg * TT;      // tile-local time index of output j=0

    const float2 d2 = reinterpret_cast<const float2*>(Dp + c0)[p];

    // K pointer for this channel pair: K[l][c0+2p] as float2 (L2-resident)
    const float2* __restrict__ Kp =
        reinterpret_cast<const float2*>(g_K) + (c0 >> 1) + p;

    float2* __restrict__ y2 =
        reinterpret_cast<float2*>(y + (size_t)b * SEQ * DM + c0);

    #pragma unroll
    for (int k = 0; k < NTILE; ++k) {
        float2 (*cur)[CBLK / 2] = (k & 1) ? buf1 : buf0;

        // prefetch tile k+1 into the other buffer
        if (k + 1 < NTILE) {
            float2 (*nxt)[CBLK / 2] = ((k + 1) & 1) ? buf1 : buf0;
            const int t0n = tbase + (k + 1) * TBLK;
            #pragma unroll
            for (int it = 0; it < ROWS * 32 / NTHR; ++it) {
                int i  = it * NTHR + tid;
                int tt = i >> 5;
                int pp = i & 31;
                int t  = t0n - 32 + tt;
                bool valid = (t >= 0) && (t < SEQ);
                cp_async8(&nxt[tt][pp],
                          u2 + (size_t)(valid ? t : 0) * (DM / 2) + pp,
                          valid ? 8u : 0u);
            }
            cp_commit();
            cp_wait<1>();    // tile k complete
        } else {
            cp_wait<0>();
        }
        __syncthreads();

        // ---- compute tile k (R3 body, K from L2) ----
        const int t0 = tbase + k * TBLK;

        float2 acc[TT];
        #pragma unroll
        for (int j = 0; j < TT; ++j)
            acc[j] = fmul2(d2, cur[lt0 + j][p]);

        float2 w[TT + G - 1];
        const int wb0 = lt0 + 32 - G;   // = lt0 + 24
        #pragma unroll
        for (int i = 0; i < TT + G - 1; ++i) w[i] = cur[wb0 + i][p];

        #pragma unroll
        for (int g = 0; g < LTAPS / G; ++g) {
            if (g > 0) {
                #pragma unroll
                for (int i = TT + G - 2; i >= G; --i) w[i] = w[i - G];
                const int wb = wb0 - g * G;
                #pragma unroll
                for (int i = 0; i < G; ++i) w[i] = cur[wb + i][p];
            }
            #pragma unroll
            for (int e = 0; e < G; ++e) {
                const int l = g * G + e;
                float2 k2 = Kp[(size_t)l * (DM / 2)];
                #pragma unroll
                for (int j = 0; j < TT; ++j)
                    acc[j] = ffma2(k2, w[j + (G - 1 - e)], acc[j]);
            }
        }

        #pragma unroll
        for (int j = 0; j < TT; ++j) {
            int t = t0 + tg * TT + j;
            y2[(size_t)t * (DM / 2) + p] = acc[j];
        }

        __syncthreads();   // cur buffer reused for prefetch at k+2
    }
}

// ---------------- launch ----------------

extern "C" void kernel_launch(void* const* d_in, const int* in_sizes, int n_in,
                              void* d_out, int out_size) {
    const float* u      = (const float*)d_in[0];
    const float* A      = (const float*)d_in[1];
    const float* Bp     = (const float*)d_in[2];
    const float* C      = (const float*)d_in[3];
    const float* Dp     = (const float*)d_in[4];
    const float* log_dt = (const float*)d_in[5];
    float* y = (float*)d_out;

    csum_part_kernel<<<64, 64>>>(C);
    kbuild_kernel<<<16, 64>>>(A, Bp, log_dt);

    // dynamic smem: 2 u buffers (2 x 48KB) = 96KB -> 2 CTAs/SM
    const int smem_bytes = (2 * ROWS * 32) * (int)sizeof(float2);
    static bool attr_set = false;
    if (!attr_set) {
        cudaFuncSetAttribute(conv_kernel,
                             cudaFuncAttributeMaxDynamicSharedMemorySize,
                             smem_bytes);
        attr_set = true;
    }

    dim3 grid(SEQ / (TBLK * NTILE), DM / CBLK, B_SZ);  // (8, 16, 8)
    conv_kernel<<<grid, NTHR, smem_bytes>>>(u, Dp, y);
}

// round 14
// speedup vs baseline: 1.2935x; 1.2935x over previous
#include <cuda_runtime.h>
#include <cstdint>

#define B_SZ 8
#define SEQ 4096
#define DM 1024
#define DS 64
#define LTAPS 64

#define TBLK 128   // time steps per block
#define CBLK 64    // channels per block (32 float2 pairs)
#define TT 8       // outputs per thread
#define NTHR 512   // conv block size
#define G 8        // tap group size

__device__ float g_part[64 * DS];   // partial C column sums
__device__ float g_K[LTAPS * DM];   // K[l][c], channel-contiguous

// ---------------- packed f32x2 ops (Blackwell FFMA2, PTX-only) ----------------

__device__ __forceinline__ float2 ffma2(float2 a, float2 b, float2 c) {
    float2 d;
    asm("fma.rn.f32x2 %0, %1, %2, %3;"
        : "=l"(*reinterpret_cast<unsigned long long*>(&d))
        : "l"(*reinterpret_cast<const unsigned long long*>(&a)),
          "l"(*reinterpret_cast<const unsigned long long*>(&b)),
          "l"(*reinterpret_cast<const unsigned long long*>(&c)));
    return d;
}

__device__ __forceinline__ float2 fmul2(float2 a, float2 b) {
    float2 d;
    asm("mul.rn.f32x2 %0, %1, %2;"
        : "=l"(*reinterpret_cast<unsigned long long*>(&d))
        : "l"(*reinterpret_cast<const unsigned long long*>(&a)),
          "l"(*reinterpret_cast<const unsigned long long*>(&b)));
    return d;
}

// ---------------- prep: stage A — partial column sums of C (coalesced) --------
__global__ __launch_bounds__(64)
void csum_part_kernel(const float* __restrict__ C) {
    const int d = threadIdx.x;
    const float* __restrict__ Cp = C + (size_t)blockIdx.x * 16 * DS + d;
    float s = 0.f;
    #pragma unroll
    for (int i = 0; i < 16; ++i) s += Cp[(size_t)i * DS];
    g_part[blockIdx.x * DS + d] = s;
}

// ---------------- prep: stage B + K build (f32x2 geometric chains) ------------
__global__ __launch_bounds__(64)
void kbuild_kernel(const float* __restrict__ A,
                   const float* __restrict__ Bp,
                   const float* __restrict__ log_dt) {
    __shared__ float sh_csum[DS];
    const int tid = threadIdx.x;

    {
        float s = 0.f;
        #pragma unroll 16
        for (int j = 0; j < 64; ++j) s += g_part[j * DS + tid];
        sh_csum[tid] = s;
    }
    __syncthreads();

    const int c = blockIdx.x * 64 + tid;
    const float dt = expf(log_dt[c]);

    float2 k2[LTAPS / 2];
    #pragma unroll
    for (int i = 0; i < LTAPS / 2; ++i) k2[i] = make_float2(0.f, 0.f);

    #pragma unroll 2
    for (int d = 0; d < DS; ++d) {
        const float w  = sh_csum[d] * Bp[(size_t)d * DM + c];
        const float r  = expf(A[d] * dt);
        const float r2 = r * r;
        float2 p = make_float2(w, w * r);
        const float2 rr = make_float2(r2, r2);
        #pragma unroll
        for (int i = 0; i < LTAPS / 2; ++i) {
            k2[i].x += p.x;
            k2[i].y += p.y;
            p = fmul2(p, rr);
        }
    }

    #pragma unroll
    for (int i = 0; i < LTAPS / 2; ++i) {
        g_K[(size_t)(2 * i)     * DM + c] = k2[i].x;
        g_K[(size_t)(2 * i + 1) * DM + c] = k2[i].y;
    }
}

// ---------------- conv kernel: NO shared memory ----------------
// y[b,t,c] = D[c]*u[b,t,c] + sum_{l=0}^{63} K[l,c] * u[b, t+31-l, c]
// 512 threads: 32 channel-pairs x 16 time groups x TT=8 outputs.
// Window reads come straight from global (coalesced 256B per warp, L1-hit
// after first touch across overlapping warps). No tile fill, no barrier.

template <bool SAFE>
__device__ __forceinline__ void conv_body(const float2* __restrict__ uw,
                                          const float2* __restrict__ Kp,
                                          float2 d2, int gt0,
                                          float2* __restrict__ yw) {
    // uw points at u[b, gt0, c0+2p]; offsets in rows (DM/2 float2 each).
    auto ld = [&](int off) -> float2 {
        if (SAFE) {
            int t = gt0 + off;
            if (t < 0 || t >= SEQ) return make_float2(0.f, 0.f);
        }
        return __ldg(uw + (ptrdiff_t)off * (DM / 2));
    };

    float2 acc[TT];
    #pragma unroll
    for (int j = 0; j < TT; ++j)
        acc[j] = fmul2(d2, ld(j));

    // register sliding window: 15 float2 covering rows [wb .. wb+14] rel gt0
    float2 w[TT + G - 1];
    const int wb0 = 32 - G;   // = 24
    #pragma unroll
    for (int i = 0; i < TT + G - 1; ++i) w[i] = ld(wb0 + i);

    #pragma unroll
    for (int g = 0; g < LTAPS / G; ++g) {
        if (g > 0) {
            #pragma unroll
            for (int i = TT + G - 2; i >= G; --i) w[i] = w[i - G];
            const int wb = wb0 - g * G;
            #pragma unroll
            for (int i = 0; i < G; ++i) w[i] = ld(wb + i);
        }
        #pragma unroll
        for (int e = 0; e < G; ++e) {
            const int l = g * G + e;
            float2 k2 = Kp[(size_t)l * (DM / 2)];
            #pragma unroll
            for (int j = 0; j < TT; ++j)
                acc[j] = ffma2(k2, w[j + (G - 1 - e)], acc[j]);
        }
    }

    #pragma unroll
    for (int j = 0; j < TT; ++j)
        yw[(ptrdiff_t)j * (DM / 2)] = acc[j];
}

__global__ __launch_bounds__(NTHR, 2)
void conv_kernel(const float* __restrict__ u,
                 const float* __restrict__ Dp,
                 float* __restrict__ y) {
    const int b  = blockIdx.z;
    const int t0 = blockIdx.x * TBLK;
    const int c0 = blockIdx.y * CBLK;
    const int tid = threadIdx.x;

    const int p   = tid & 31;          // channel pair
    const int tg  = tid >> 5;          // time group (0..15)
    const int gt0 = t0 + tg * TT;      // global time of output j=0

    const float2* __restrict__ uw =
        reinterpret_cast<const float2*>(u + (size_t)b * SEQ * DM + c0)
        + (size_t)gt0 * (DM / 2) + p;

    const float2* __restrict__ Kp =
        reinterpret_cast<const float2*>(g_K) + (c0 >> 1) + p;

    const float2 d2 = reinterpret_cast<const float2*>(Dp + c0)[p];

    float2* __restrict__ yw =
        reinterpret_cast<float2*>(y + (size_t)b * SEQ * DM + c0)
        + (size_t)gt0 * (DM / 2) + p;

    // window spans rows gt0-32 .. gt0+38; interior blocks need no predication
    if (t0 >= 32 && t0 + TBLK + 39 <= SEQ) {
        conv_body<false>(uw, Kp, d2, gt0, yw);
    } else {
        conv_body<true>(uw, Kp, d2, gt0, yw);
    }
}

// ---------------- launch ----------------

extern "C" void kernel_launch(void* const* d_in, const int* in_sizes, int n_in,
                              void* d_out, int out_size) {
    const float* u      = (const float*)d_in[0];
    const float* A      = (const float*)d_in[1];
    const float* Bp     = (const float*)d_in[2];
    const float* C      = (const float*)d_in[3];
    const float* Dp     = (const float*)d_in[4];
    const float* log_dt = (const float*)d_in[5];
    float* y = (float*)d_out;

    csum_part_kernel<<<64, 64>>>(C);
    kbuild_kernel<<<16, 64>>>(A, Bp, log_dt);

    dim3 grid(SEQ / TBLK, DM / CBLK, B_SZ);  // (32, 16, 8)
    conv_kernel<<<grid, NTHR>>>(u, Dp, y);
}